// round 9
// baseline (speedup 1.0000x reference)
#include <cuda_runtime.h>
#include <cuda_bf16.h>

// DiagPooling: x [B=8, C=128, H=512, W=512] fp32 -> out [B, 1, 513] fp32
// out[b, 0, o] = (1 / (128 * (512 - |o-256|))) * sum_{c,i} x[b, c, i, i + o - 256]
//
// Convergence commit. Evidence across 8 rounds: traffic is compulsory
// (~843 MB incl. edge-sector padding) and achieved BW is pinned at
// ~6.63 TB/s = the chip's path-independent LTS throughput cap at the
// sustained clock (6300 B/cyc x ~1.05 GHz). Kernel floor ~127.1 us; the
// R8 kernel measured 126.9 us. This round pairs that kernel (LPT block
// order: widest rows first so the drain tail holds the shortest blocks)
// with the cheap zero kernel (1.2 us overhead, beats the 2.2 us
// cudaMemsetAsync graph node measured in R8).
//
// Mapping: block = (xblk -> row i by descending width, batch b),
// 512 threads; thread t owns column j = j0 + t (coalesced), sums all 128
// channels in registers (4 accumulators, unroll 8), then one pre-scaled
// atomicAdd into out[b*513 + (j - i + 256)]. 1.57M REDG over 4104
// addresses (~384 serialized updates/addr -> off the critical path).

#define B_DIM 8
#define C_DIM 128
#define H_DIM 512
#define W_DIM 512
#define N_OFF 513
#define OUT_ELEMS (B_DIM * N_OFF)

__global__ void zero_out_kernel(float* __restrict__ out, int n) {
    int idx = blockIdx.x * blockDim.x + threadIdx.x;
    if (idx < n) out[idx] = 0.0f;
}

__global__ __launch_bounds__(512) void diag_pool_kernel(
    const float* __restrict__ x, float* __restrict__ out)
{
    // LPT row permutation: widest rows (middle) first, narrowest (edges) last
    const int xblk = blockIdx.x;                 // 0..511
    const int d = 255 - (xblk >> 1);             // 255..0
    const int i = (xblk & 1) ? (511 - d) : d;    // row, width-descending order

    const int b = blockIdx.y;                    // batch 0..7
    const int t = threadIdx.x;                   // 0..511

    // Valid column range for this row: |j - i| <= 256
    const int j0 = (i - 256 > 0) ? (i - 256) : 0;
    const int j1 = (i + 256 < H_DIM - 1) ? (i + 256) : (H_DIM - 1);
    const int j = j0 + t;
    if (j > j1) return;

    // Base pointer: x[b, 0, i, j]; channel stride = H*W elements
    const size_t ch_stride = (size_t)H_DIM * W_DIM;
    const float* p = x + ((size_t)b * C_DIM * H_DIM + (size_t)i) * W_DIM + j;

    // Sum over all 128 channels with 4 independent accumulators
    float s0 = 0.f, s1 = 0.f, s2 = 0.f, s3 = 0.f;
    #pragma unroll 8
    for (int c = 0; c < C_DIM; c += 4) {
        s0 += __ldg(p + (size_t)(c + 0) * ch_stride);
        s1 += __ldg(p + (size_t)(c + 1) * ch_stride);
        s2 += __ldg(p + (size_t)(c + 2) * ch_stride);
        s3 += __ldg(p + (size_t)(c + 3) * ch_stride);
    }
    const float s = (s0 + s1) + (s2 + s3);

    // Diagonal/output index and normalization
    const int o = j - i + 256;                   // 0..512, unique within block
    const int off = o - 256;
    const int diag_len = H_DIM - (off < 0 ? -off : off);
    const float denom = (float)C_DIM * (float)diag_len;

    atomicAdd(&out[b * N_OFF + o], s / denom);
}

extern "C" void kernel_launch(void* const* d_in, const int* in_sizes, int n_in,
                              void* d_out, int out_size) {
    const float* x = (const float*)d_in[0];
    float* out = (float*)d_out;

    zero_out_kernel<<<(OUT_ELEMS + 255) / 256, 256>>>(out, OUT_ELEMS);

    dim3 grid(H_DIM, B_DIM);
    diag_pool_kernel<<<grid, 512>>>(x, out);
}

// round 10
// speedup vs baseline: 1.0156x; 1.0156x over previous
#include <cuda_runtime.h>
#include <cuda_bf16.h>

// DiagPooling: x [B=8, C=128, H=512, W=512] fp32 -> out [B, 1, 513] fp32
// out[b, 0, o] = (1 / (128 * (512 - |o-256|))) * sum_{c,i} x[b, c, i, i + o - 256]
//
// SINGLE-LAUNCH version. The memory kernel is pinned at the chip's
// path-independent LTS throughput cap (~6.63 TB/s -> ~127.1 us for the
// compulsory ~843 MB); the only recoverable time left is the separate
// zero-init launch (~2 us of launch + node-gap). Fusion protocol:
//   - blocks bid 0..7 (blockIdx.y==0, x<8; guaranteed first-wave) zero
//     out[] before their load loop, __threadfence, atomicAdd(g_zero_done).
//   - every block does its ~14us load loop FIRST, then thread0 spins until
//     g_zero_done==8 (already satisfied ~10us earlier -> single poll; no
//     deadlock possible: zeroers are dependency-free and first-wave).
//   - atomics to out only after the handshake + __syncthreads.
//   - last block (g_blocks_finished==4095) resets both counters so every
//     graph replay performs identical work (statics start at 0, so the
//     first call is also correct).
// Work mapping identical to the floor kernel: block=(row i via LPT
// permutation, batch b), 512 threads, thread t = column j0+t, 128-channel
// register reduction (4 accumulators, unroll 8), one pre-scaled atomicAdd.

#define B_DIM 8
#define C_DIM 128
#define H_DIM 512
#define W_DIM 512
#define N_OFF 513
#define OUT_ELEMS (B_DIM * N_OFF)
#define NBLOCKS_TOTAL (H_DIM * B_DIM)   // 4096

__device__ int g_zero_done;        // zero-initialized at module load
__device__ int g_blocks_finished;  // zero-initialized at module load

__global__ __launch_bounds__(512) void diag_pool_kernel(
    const float* __restrict__ x, float* __restrict__ out)
{
    const int xblk = blockIdx.x;                 // 0..511
    const int b    = blockIdx.y;                 // 0..7
    const int t    = threadIdx.x;                // 0..511

    // ---- fused zero-init: first 8 blocks (bid 0..7) zero one batch each ----
    if (b == 0 && xblk < B_DIM) {
        float* dst = out + xblk * N_OFF;
        if (t < N_OFF) dst[t] = 0.0f;            // t covers 0..511
        if (t == 0) dst[512] = 0.0f;
        __syncthreads();                         // all zero stores issued
        if (t == 0) {
            __threadfence();                     // zeros visible at L2
            atomicAdd(&g_zero_done, 1);
        }
    }

    // ---- main work (LPT row order: widest rows first) ----
    const int d = 255 - (xblk >> 1);
    const int i = (xblk & 1) ? (511 - d) : d;

    const int j0 = (i - 256 > 0) ? (i - 256) : 0;
    const int j1 = (i + 256 < H_DIM - 1) ? (i + 256) : (H_DIM - 1);
    const int j = j0 + t;
    const bool active = (j <= j1);               // no early return (syncthreads below)

    float s = 0.0f;
    if (active) {
        const size_t ch_stride = (size_t)H_DIM * W_DIM;
        const float* p = x + ((size_t)b * C_DIM * H_DIM + (size_t)i) * W_DIM + j;

        float s0 = 0.f, s1 = 0.f, s2 = 0.f, s3 = 0.f;
        #pragma unroll 8
        for (int c = 0; c < C_DIM; c += 4) {
            s0 += __ldg(p + (size_t)(c + 0) * ch_stride);
            s1 += __ldg(p + (size_t)(c + 1) * ch_stride);
            s2 += __ldg(p + (size_t)(c + 2) * ch_stride);
            s3 += __ldg(p + (size_t)(c + 3) * ch_stride);
        }
        s = (s0 + s1) + (s2 + s3);
    }

    // ---- handshake: zeros must be in place before accumulation ----
    if (t == 0) {
        while (*(volatile int*)&g_zero_done < B_DIM) { /* spin (1 poll typ.) */ }
    }
    __syncthreads();

    if (active) {
        const int o = j - i + 256;               // diagonal id 0..512
        const int off = o - 256;
        const int dlen = H_DIM - (off < 0 ? -off : off);
        atomicAdd(&out[b * N_OFF + o], s / ((float)C_DIM * (float)dlen));
    }

    // ---- epoch reset so the next graph replay starts clean ----
    if (t == 0) {
        const int old = atomicAdd(&g_blocks_finished, 1);
        if (old == NBLOCKS_TOTAL - 1) {          // last block: all spins passed
            g_zero_done = 0;
            g_blocks_finished = 0;
            __threadfence();
        }
    }
}

extern "C" void kernel_launch(void* const* d_in, const int* in_sizes, int n_in,
                              void* d_out, int out_size) {
    const float* x = (const float*)d_in[0];
    float* out = (float*)d_out;

    dim3 grid(H_DIM, B_DIM);                     // 4096 blocks, one launch
    diag_pool_kernel<<<grid, 512>>>(x, out);
}